// round 11
// baseline (speedup 1.0000x reference)
#include <cuda_runtime.h>

// AtomicNeuralNetwork: species-routed per-atom MLP [39 -> 50 silu -> 50 silu -> 1]
// Register-tiled rewrite after R8 profile showed L1=71.4% / fma=37%:
// uniform LDS.128 broadcasts still cost full 512B/warp register writeback, so
// the old per-thread-sample structure was LDS-return-bandwidth bound.
// New structure: thread = 8 samples x 8 hidden tile -> 2KB return per 32 FFMA2
// per warp per k (64B/FFMA2), exactly balancing LSU return (128B/cyc/SM)
// against the f32x2 FMA pipe (2 FFMA2/cyc/SM).
//
// CTA: 224 threads = 7 warps (warp = 8-hidden group, hidden padded 50->56),
// 256 samples (lane = sample group, samples strided by 32 so every x LDS.32
// and inter-layer STS.32 is lane-consecutive -> conflict-free).
// Sample-major tiles use row stride 257 (odd) so the staging transpose
// (consecutive lanes -> consecutive rows) is also bank-conflict-free.
// H2 tile aliases the dead X tile. Smem ~130KB -> occupancy 1.

#define NN   4096
#define AA   256
#define DIN  39
#define HH   50
#define HP   56          // padded hidden: 7 warps x 8
#define TPB  224
#define SCTA 256         // samples per CTA
#define XSTR 257         // padded stride for sample-major tiles (odd)

// ---- smem float offsets (W1/W2 bases kept 16B-aligned) ----
#define OFF_XH2 0                          // union: XT[39][257] / H2T[50][257]
#define SZ_XH2  (HH * XSTR)                // 12850
#define OFF_H1  (OFF_XH2 + SZ_XH2)        // H1T[56][257]
#define OFF_W1  (((OFF_H1 + HP * XSTR) + 3) & ~3)   // 16B aligned
#define OFF_W2  (OFF_W1 + DIN * HP)        // 56%4==0 keeps alignment
#define OFF_B1  (OFF_W2 + HH * HP)
#define OFF_B2  (OFF_B1 + HP)
#define OFF_W3  (OFF_B2 + HP)
#define OFF_B3  (OFF_W3 + HP)
#define SMEM_FLOATS (OFF_B3 + 4)
#define SMEM_BYTES  (SMEM_FLOATS * 4)      // ~129.6 KB

typedef unsigned long long u64;

__device__ __forceinline__ u64 pack2_dup(float v) {
    u64 r; asm("mov.b64 %0, {%1, %1};" : "=l"(r) : "f"(v)); return r;
}
__device__ __forceinline__ void unpack2(u64 v, float& lo, float& hi) {
    asm("mov.b64 {%0, %1}, %2;" : "=f"(lo), "=f"(hi) : "l"(v));
}
// packed dual-FMA: d = a*b + c on both f32 lanes
__device__ __forceinline__ u64 fma2(u64 a, u64 b, u64 c) {
    u64 d; asm("fma.rn.f32x2 %0, %1, %2, %3;" : "=l"(d) : "l"(a), "l"(b), "l"(c));
    return d;
}
__device__ __forceinline__ float silu_f(float v) {
    return __fdividef(v, 1.0f + __expf(-v));   // MUFU.EX2 + MUFU.RCP
}

extern __shared__ float smem[];

__global__ void __launch_bounds__(TPB, 1)
atomic_mlp_kernel(const float* __restrict__ desc,
                  const int*   __restrict__ numbers,
                  const float* __restrict__ W1, const float* __restrict__ B1,
                  const float* __restrict__ W2, const float* __restrict__ B2,
                  const float* __restrict__ W3, const float* __restrict__ B3,
                  float* __restrict__ out)
{
    float* sXT = smem + OFF_XH2;  // XT[39][257], later reused as H2T[50][257]
    float* sH2 = smem + OFF_XH2;
    float* sH1 = smem + OFF_H1;   // H1T[56][257]
    float* sW1 = smem + OFF_W1;   // [39][56] k-major, padded cols zero
    float* sW2 = smem + OFF_W2;   // [50][56]
    float* sB1 = smem + OFF_B1;
    float* sB2 = smem + OFF_B2;
    float* sW3 = smem + OFF_W3;
    float* sB3 = smem + OFF_B3;

    const int a    = blockIdx.x;     // atom
    const int tile = blockIdx.y;     // 256-sample tile
    const int tid  = threadIdx.x;
    const int hg   = tid >> 5;       // warp id = hidden group (0..6)
    const int sg   = tid & 31;       // lane  = sample group (samples sg+32j)
    const int s    = numbers[a];     // species

    // ---- staging: desc tile transposed into XT[d][sample] (stride 257) ----
    // LDG coalesced (consecutive i -> consecutive d within a sample row);
    // STS lanes differ by XSTR=257 (odd) -> conflict-free.
    {
        const float* base = desc + ((long)tile * SCTA * AA + a) * DIN;
        for (int i = tid; i < SCTA * DIN; i += TPB) {
            int r = i / DIN, c = i - r * DIN;
            sXT[c * XSTR + r] = base[(long)r * AA * DIN + c];
        }
    }
    // ---- weights (k-major, hidden padded to 56 with zeros) ----
    for (int i = tid; i < DIN * HP; i += TPB) {
        int k = i / HP, h = i - k * HP;
        sW1[i] = (h < HH) ? W1[(s * DIN + k) * HH + h] : 0.0f;
    }
    for (int i = tid; i < HH * HP; i += TPB) {
        int k = i / HP, h = i - k * HP;
        sW2[i] = (h < HH) ? W2[(s * HH + k) * HH + h] : 0.0f;
    }
    if (tid < HP) {
        sB1[tid] = (tid < HH) ? B1[s * HH + tid] : 0.0f;
        sB2[tid] = (tid < HH) ? B2[s * HH + tid] : 0.0f;
        sW3[tid] = (tid < HH) ? W3[s * HH + tid] : 0.0f;
    }
    if (tid == 0) sB3[0] = B3[s];
    __syncthreads();

    // ================= layer 1: [39] -> hidden tile =================
    u64 acc[8][4];                       // [sample j][hidden pair p]
    {
        const u64* bp = (const u64*)(sB1 + hg * 8);
        u64 b0 = bp[0], b1 = bp[1], b2 = bp[2], b3v = bp[3];
        #pragma unroll
        for (int j = 0; j < 8; j++) {
            acc[j][0] = b0; acc[j][1] = b1; acc[j][2] = b2; acc[j][3] = b3v;
        }
    }
    #pragma unroll 2
    for (int k = 0; k < DIN; k++) {
        const float* xr = sXT + k * XSTR + sg;
        u64 xv[8];
        #pragma unroll
        for (int j = 0; j < 8; j++) xv[j] = pack2_dup(xr[32 * j]);
        const ulonglong2* wp = (const ulonglong2*)(sW1 + k * HP + hg * 8);
        ulonglong2 wa = wp[0], wb = wp[1];       // 4 hidden pairs
        #pragma unroll
        for (int j = 0; j < 8; j++) {
            acc[j][0] = fma2(xv[j], wa.x, acc[j][0]);
            acc[j][1] = fma2(xv[j], wa.y, acc[j][1]);
            acc[j][2] = fma2(xv[j], wb.x, acc[j][2]);
            acc[j][3] = fma2(xv[j], wb.y, acc[j][3]);
        }
    }
    // silu + store to H1T (lanes consecutive -> conflict-free STS.32)
    #pragma unroll
    for (int p = 0; p < 4; p++) {
        float* r0 = sH1 + (hg * 8 + 2 * p) * XSTR + sg;
        float* r1 = r0 + XSTR;
        #pragma unroll
        for (int j = 0; j < 8; j++) {
            float lo, hi; unpack2(acc[j][p], lo, hi);
            r0[32 * j] = silu_f(lo);
            r1[32 * j] = silu_f(hi);
        }
    }
    __syncthreads();

    // ================= layer 2: [50] -> hidden tile =================
    {
        const u64* bp = (const u64*)(sB2 + hg * 8);
        u64 b0 = bp[0], b1 = bp[1], b2 = bp[2], b3v = bp[3];
        #pragma unroll
        for (int j = 0; j < 8; j++) {
            acc[j][0] = b0; acc[j][1] = b1; acc[j][2] = b2; acc[j][3] = b3v;
        }
    }
    #pragma unroll 2
    for (int k = 0; k < HH; k++) {
        const float* xr = sH1 + k * XSTR + sg;
        u64 xv[8];
        #pragma unroll
        for (int j = 0; j < 8; j++) xv[j] = pack2_dup(xr[32 * j]);
        const ulonglong2* wp = (const ulonglong2*)(sW2 + k * HP + hg * 8);
        ulonglong2 wa = wp[0], wb = wp[1];
        #pragma unroll
        for (int j = 0; j < 8; j++) {
            acc[j][0] = fma2(xv[j], wa.x, acc[j][0]);
            acc[j][1] = fma2(xv[j], wa.y, acc[j][1]);
            acc[j][2] = fma2(xv[j], wb.x, acc[j][2]);
            acc[j][3] = fma2(xv[j], wb.y, acc[j][3]);
        }
    }
    // silu + store rows h<50 into H2T (aliases XT; all XT reads done pre-sync)
    #pragma unroll
    for (int p = 0; p < 4; p++) {
        int h0 = hg * 8 + 2 * p;
        #pragma unroll
        for (int j = 0; j < 8; j++) {
            float lo, hi; unpack2(acc[j][p], lo, hi);
            if (h0 < HH)     sH2[h0 * XSTR + sg + 32 * j]       = silu_f(lo);
            if (h0 + 1 < HH) sH2[(h0 + 1) * XSTR + sg + 32 * j] = silu_f(hi);
        }
    }
    __syncthreads();

    // ================= layer 3: dot with w3 =================
    const float b3s = sB3[0];
    for (int s0 = tid; s0 < SCTA; s0 += TPB) {
        float accv = b3s;
        for (int k = 0; k < HH; k++)
            accv = fmaf(sH2[k * XSTR + s0], sW3[k], accv);
        out[((long)(tile * SCTA + s0)) * AA + a] = accv;
    }
}

extern "C" void kernel_launch(void* const* d_in, const int* in_sizes, int n_in,
                              void* d_out, int out_size)
{
    const float* desc    = (const float*)d_in[0];
    const int*   numbers = (const int*)  d_in[1];
    const float* W1      = (const float*)d_in[2];
    const float* B1      = (const float*)d_in[3];
    const float* W2      = (const float*)d_in[4];
    const float* B2      = (const float*)d_in[5];
    const float* W3      = (const float*)d_in[6];
    const float* B3      = (const float*)d_in[7];
    float* out = (float*)d_out;

    cudaFuncSetAttribute(atomic_mlp_kernel,
                         cudaFuncAttributeMaxDynamicSharedMemorySize,
                         SMEM_BYTES);

    dim3 grid(AA, NN / SCTA);   // 256 atoms x 16 sample tiles
    atomic_mlp_kernel<<<grid, TPB, SMEM_BYTES>>>(desc, numbers,
                                                 W1, B1, W2, B2, W3, B3, out);
}

// round 12
// speedup vs baseline: 1.4587x; 1.4587x over previous
#include <cuda_runtime.h>

// AtomicNeuralNetwork: species-routed per-atom MLP [39 -> 50 silu -> 50 silu -> 1]
// R11 post-mortem: 8x8 register tiling cut L1 activity to ~255K cyc (on model)
// but at 7 warps/SM the kernel went latency-bound (fma 25%, issue 25.6%).
// R12: identical per-warp structure, 14 warps/CTA:
//   warp = (hidden group 0..6) x (sample half 0..1), SCTA=512, TPB=448.
// Layer-3 computed from acc2 registers (per-warp partial dot with w3) and
// reduced via sPart[7][513] aliased onto the dead X tile -> no H2 tile.
// Smem ~198.5KB (occ 1), regs ~110 < 146 cap (unroll 1), 2048 CTAs.
// Per-SM per k: fma 14x32 FFMA2 = 224 cyc, L1 14x16 wf = 224 cyc -> balanced.

#define NN   4096
#define AA   256
#define DIN  39
#define HH   50
#define HP   56          // padded hidden: 7 groups x 8
#define TPB  448         // 14 warps
#define SCTA 512         // samples per CTA
#define XSTR 513         // odd stride: conflict-free transpose

// ---- smem float offsets ----
#define OFF_XT  0                          // XT[39][513]; later sPart[7][513]
#define OFF_H1  (OFF_XT + DIN * XSTR)      // H1[50][513]
#define OFF_W1  (((OFF_H1 + HH * XSTR) + 3) & ~3)
#define OFF_W2  (OFF_W1 + DIN * HP)
#define OFF_B1  (OFF_W2 + HH * HP)
#define OFF_B2  (OFF_B1 + HP)
#define OFF_W3  (OFF_B2 + HP)
#define OFF_B3  (OFF_W3 + HP)
#define SMEM_FLOATS (OFF_B3 + 4)
#define SMEM_BYTES  (SMEM_FLOATS * 4)      // ~198.6 KB

typedef unsigned long long u64;

__device__ __forceinline__ u64 pack2_dup(float v) {
    u64 r; asm("mov.b64 %0, {%1, %1};" : "=l"(r) : "f"(v)); return r;
}
__device__ __forceinline__ void unpack2(u64 v, float& lo, float& hi) {
    asm("mov.b64 {%0, %1}, %2;" : "=f"(lo), "=f"(hi) : "l"(v));
}
__device__ __forceinline__ u64 fma2(u64 a, u64 b, u64 c) {
    u64 d; asm("fma.rn.f32x2 %0, %1, %2, %3;" : "=l"(d) : "l"(a), "l"(b), "l"(c));
    return d;
}
__device__ __forceinline__ float silu_f(float v) {
    return __fdividef(v, 1.0f + __expf(-v));   // MUFU.EX2 + MUFU.RCP
}

extern __shared__ float smem[];

__global__ void __launch_bounds__(TPB, 1)
atomic_mlp_kernel(const float* __restrict__ desc,
                  const int*   __restrict__ numbers,
                  const float* __restrict__ W1, const float* __restrict__ B1,
                  const float* __restrict__ W2, const float* __restrict__ B2,
                  const float* __restrict__ W3, const float* __restrict__ B3,
                  float* __restrict__ out)
{
    float* sXT = smem + OFF_XT;   // XT[39][513] during layers 1; sPart after
    float* sPt = smem + OFF_XT;   // sPart[7][513] (alias; barrier-separated)
    float* sH1 = smem + OFF_H1;   // H1[50][513]
    float* sW1 = smem + OFF_W1;   // [39][56] k-major, padded cols zero
    float* sW2 = smem + OFF_W2;   // [50][56]
    float* sB1 = smem + OFF_B1;
    float* sB2 = smem + OFF_B2;
    float* sW3 = smem + OFF_W3;
    float* sB3 = smem + OFF_B3;

    const int a    = blockIdx.x;       // atom
    const int tile = blockIdx.y;       // 512-sample tile
    const int tid  = threadIdx.x;
    const int wid  = tid >> 5;
    const int sg   = tid & 31;
    const int hg   = wid % 7;          // hidden group (8 hidden each)
    const int sh   = wid / 7;          // sample half (0/1)
    const int sbase = sh * 256;        // this warp's sample offset
    const int s    = numbers[a];       // species

    // ---- staging: transpose desc tile into XT[d][sample] ----
    {
        const float* base = desc + (long)tile * SCTA * AA * DIN + (long)a * DIN;
        for (int i = tid; i < SCTA * DIN; i += TPB) {
            int r = i / DIN, c = i - r * DIN;
            sXT[c * XSTR + r] = base[(long)r * AA * DIN + c];
        }
    }
    // ---- weights (k-major, hidden padded to 56 with zeros) ----
    for (int i = tid; i < DIN * HP; i += TPB) {
        int k = i / HP, h = i - k * HP;
        sW1[i] = (h < HH) ? W1[(s * DIN + k) * HH + h] : 0.0f;
    }
    for (int i = tid; i < HH * HP; i += TPB) {
        int k = i / HP, h = i - k * HP;
        sW2[i] = (h < HH) ? W2[(s * HH + k) * HH + h] : 0.0f;
    }
    if (tid < HP) {
        sB1[tid] = (tid < HH) ? B1[s * HH + tid] : 0.0f;
        sB2[tid] = (tid < HH) ? B2[s * HH + tid] : 0.0f;
        sW3[tid] = (tid < HH) ? W3[s * HH + tid] : 0.0f;
    }
    if (tid == 0) sB3[0] = B3[s];
    __syncthreads();

    // ================= layer 1: [39] -> 8-hidden tile =================
    u64 acc[8][4];                       // [sample j][hidden pair p]
    {
        const u64* bp = (const u64*)(sB1 + hg * 8);
        u64 b0 = bp[0], b1 = bp[1], b2 = bp[2], b3v = bp[3];
        #pragma unroll
        for (int j = 0; j < 8; j++) {
            acc[j][0] = b0; acc[j][1] = b1; acc[j][2] = b2; acc[j][3] = b3v;
        }
    }
    #pragma unroll 1
    for (int k = 0; k < DIN; k++) {
        const float* xr = sXT + k * XSTR + sbase + sg;
        u64 xv[8];
        #pragma unroll
        for (int j = 0; j < 8; j++) xv[j] = pack2_dup(xr[32 * j]);
        const ulonglong2* wp = (const ulonglong2*)(sW1 + k * HP + hg * 8);
        ulonglong2 wa = wp[0], wb = wp[1];
        #pragma unroll
        for (int j = 0; j < 8; j++) {
            acc[j][0] = fma2(xv[j], wa.x, acc[j][0]);
            acc[j][1] = fma2(xv[j], wa.y, acc[j][1]);
            acc[j][2] = fma2(xv[j], wb.x, acc[j][2]);
            acc[j][3] = fma2(xv[j], wb.y, acc[j][3]);
        }
    }
    // silu + store rows h<50 to H1 (lane-dense STS.32, conflict-free)
    #pragma unroll
    for (int p = 0; p < 4; p++) {
        int h0 = hg * 8 + 2 * p;
        #pragma unroll
        for (int j = 0; j < 8; j++) {
            float lo, hi; unpack2(acc[j][p], lo, hi);
            if (h0 < HH)     sH1[h0 * XSTR + sbase + sg + 32 * j]       = silu_f(lo);
            if (h0 + 1 < HH) sH1[(h0 + 1) * XSTR + sbase + sg + 32 * j] = silu_f(hi);
        }
    }
    __syncthreads();   // all XT reads done; sPt (alias) now writable

    // ================= layer 2: [50] -> 8-hidden tile =================
    {
        const u64* bp = (const u64*)(sB2 + hg * 8);
        u64 b0 = bp[0], b1 = bp[1], b2 = bp[2], b3v = bp[3];
        #pragma unroll
        for (int j = 0; j < 8; j++) {
            acc[j][0] = b0; acc[j][1] = b1; acc[j][2] = b2; acc[j][3] = b3v;
        }
    }
    #pragma unroll 1
    for (int k = 0; k < HH; k++) {
        const float* xr = sH1 + k * XSTR + sbase + sg;
        u64 xv[8];
        #pragma unroll
        for (int j = 0; j < 8; j++) xv[j] = pack2_dup(xr[32 * j]);
        const ulonglong2* wp = (const ulonglong2*)(sW2 + k * HP + hg * 8);
        ulonglong2 wa = wp[0], wb = wp[1];
        #pragma unroll
        for (int j = 0; j < 8; j++) {
            acc[j][0] = fma2(xv[j], wa.x, acc[j][0]);
            acc[j][1] = fma2(xv[j], wa.y, acc[j][1]);
            acc[j][2] = fma2(xv[j], wb.x, acc[j][2]);
            acc[j][3] = fma2(xv[j], wb.y, acc[j][3]);
        }
    }

    // ===== layer 3 partials: silu(acc2) . w3 over this warp's 8 hidden =====
    // w3 pad (h>=50) is zero, so padded lanes contribute exactly 0.
    {
        const u64* w3p = (const u64*)(sW3 + hg * 8);
        u64 w0 = w3p[0], w1v = w3p[1], w2v = w3p[2], w3v = w3p[3];
        #pragma unroll
        for (int j = 0; j < 8; j++) {
            float lo, hi;
            u64 pacc = 0ull;
            unpack2(acc[j][0], lo, hi);
            u64 hv; asm("mov.b64 %0, {%1, %2};" : "=l"(hv) : "f"(silu_f(lo)), "f"(silu_f(hi)));
            pacc = fma2(hv, w0, pacc);
            unpack2(acc[j][1], lo, hi);
            asm("mov.b64 %0, {%1, %2};" : "=l"(hv) : "f"(silu_f(lo)), "f"(silu_f(hi)));
            pacc = fma2(hv, w1v, pacc);
            unpack2(acc[j][2], lo, hi);
            asm("mov.b64 %0, {%1, %2};" : "=l"(hv) : "f"(silu_f(lo)), "f"(silu_f(hi)));
            pacc = fma2(hv, w2v, pacc);
            unpack2(acc[j][3], lo, hi);
            asm("mov.b64 %0, {%1, %2};" : "=l"(hv) : "f"(silu_f(lo)), "f"(silu_f(hi)));
            pacc = fma2(hv, w3v, pacc);
            float plo, phi; unpack2(pacc, plo, phi);
            sPt[hg * XSTR + sbase + sg + 32 * j] = plo + phi;
        }
    }
    __syncthreads();

    // ===== final: deterministic 7-way reduce + bias, store out =====
    const float b3s = sB3[0];
    for (int s0 = tid; s0 < SCTA; s0 += TPB) {
        float v = b3s;
        #pragma unroll
        for (int g = 0; g < 7; g++) v += sPt[g * XSTR + s0];
        out[((long)(tile * SCTA + s0)) * AA + a] = v;
    }
}

extern "C" void kernel_launch(void* const* d_in, const int* in_sizes, int n_in,
                              void* d_out, int out_size)
{
    const float* desc    = (const float*)d_in[0];
    const int*   numbers = (const int*)  d_in[1];
    const float* W1      = (const float*)d_in[2];
    const float* B1      = (const float*)d_in[3];
    const float* W2      = (const float*)d_in[4];
    const float* B2      = (const float*)d_in[5];
    const float* W3      = (const float*)d_in[6];
    const float* B3      = (const float*)d_in[7];
    float* out = (float*)d_out;

    cudaFuncSetAttribute(atomic_mlp_kernel,
                         cudaFuncAttributeMaxDynamicSharedMemorySize,
                         SMEM_BYTES);

    dim3 grid(AA, NN / SCTA);   // 256 atoms x 8 sample tiles = 2048 CTAs
    atomic_mlp_kernel<<<grid, TPB, SMEM_BYTES>>>(desc, numbers,
                                                 W1, B1, W2, B2, W3, B3, out);
}